// round 11
// baseline (speedup 1.0000x reference)
#include <cuda_runtime.h>
#include <cuda_fp16.h>
#include <cstdint>
#include <cstddef>

// ---------------- SMEM layout (bytes) ----------------
// Q  : [64 rows][256 d] fp16, row stride 512B, 16B-chunk XOR swizzle -> 32KB
// KV : [128 rows][256 d] fp16, same layout -> 64KB (K for S, V (trans) for PV)
// P  : [64 rows][128 kv] fp16, row stride 256B -> 16KB
// RS : float[64][4] ALIASED over P (P dead after last PV; sync separates uses)
#define SM_Q   0
#define SM_KV  32768
#define SM_P   98304
#define SM_RS  98304
#define SMEM_BYTES 114688

// ---------------- helpers ----------------
__device__ __forceinline__ uint32_t smem_u32(const void* p) {
    uint32_t a;
    asm("{ .reg .u64 t; cvta.to.shared.u64 t, %1; cvt.u32.u64 %0, t; }" : "=r"(a) : "l"(p));
    return a;
}
// pack two fp32 -> fp16x2, a in LOW half
__device__ __forceinline__ uint32_t f2h2(float a, float b) {
    uint32_t r;
    asm("cvt.rn.f16x2.f32 %0, %2, %1;" : "=r"(r) : "f"(a), "f"(b));
    return r;
}
__device__ __forceinline__ float ex2(float x) {
    float r;
    asm("ex2.approx.f32 %0, %1;" : "=f"(r) : "f"(x));
    return r;
}

#define STS32(addr, v) \
    asm volatile("st.shared.b32 [%0], %1;" :: "r"(addr), "r"(v) : "memory")
#define STS64(addr, v0, v1) \
    asm volatile("st.shared.v2.b32 [%0], {%1, %2};" :: "r"(addr), "r"(v0), "r"(v1) : "memory")

#define LDSM_X4(r0, r1, r2, r3, addr)                                          \
    asm volatile("ldmatrix.sync.aligned.m8n8.x4.shared.b16 {%0,%1,%2,%3}, [%4];" \
        : "=r"(r0), "=r"(r1), "=r"(r2), "=r"(r3) : "r"(addr))
#define LDSM_X4_T(r0, r1, r2, r3, addr)                                        \
    asm volatile("ldmatrix.sync.aligned.m8n8.x4.trans.shared.b16 {%0,%1,%2,%3}, [%4];" \
        : "=r"(r0), "=r"(r1), "=r"(r2), "=r"(r3) : "r"(addr))

// D(f32x4) += A(f16, m16k16) * B(f16, k16n8)
#define MMA(c, a0, a1, a2, a3, b0, b1)                                         \
    asm volatile("mma.sync.aligned.m16n8k16.row.col.f32.f16.f16.f32 "          \
        "{%0,%1,%2,%3},{%4,%5,%6,%7},{%8,%9},{%0,%1,%2,%3};"                   \
        : "+f"((c)[0]), "+f"((c)[1]), "+f"((c)[2]), "+f"((c)[3])               \
        : "r"(a0), "r"(a1), "r"(a2), "r"(a3), "r"(b0), "r"(b1))

// ---------------- kernel ----------------
// grid 1024 = 64 batches x 16 q-tiles of 64 rows; block 256 = 8 warps; 2 CTAs/SM.
// S  phase: warp w -> rows [32*(w>>2), +32), kv cols [32*(w&3), +32)   (m32 x n32)
// PV phase: warp w -> rows [32*(w>>2), +32), d  cols [64*(w&3), +64)   (m32 x n64)
// Co-resident CTA fills barrier/load bubbles (no register prefetch -> no spills).
__global__ void __launch_bounds__(256, 2)
attn_kernel(const float* __restrict__ q, const float* __restrict__ kv,
            float* __restrict__ out)
{
    extern __shared__ __align__(16) char smem[];
    const uint32_t sb = smem_u32(smem);
    const int tid  = threadIdx.x;
    const int lane = tid & 31, w = tid >> 5;
    const int b  = blockIdx.x >> 4;
    const int q0 = (blockIdx.x & 15) << 6;
    const int g = lane >> 2, tig = lane & 3;
    const int lj = lane & 7, sel = lane >> 3;
    const uint32_t swl = (uint32_t)lj << 4;
    const uint32_t gx  = (uint32_t)g << 4;

    const int m0  = (w >> 2) << 5;      // row base: 0 or 32
    const int n0s = (w & 3) << 5;       // S kv-quarter base
    const int d0q = (w & 3) << 6;       // PV d-quarter base

    // fragment lane geometry (validated R8-R10)
    const uint32_t colselA = (uint32_t)(sel >> 1) << 4;  // A-type and V-trans
    const uint32_t colselB = (uint32_t)(sel & 1) << 4;   // B-type non-trans
    const int rA = lj + ((sel & 1) << 3);
    const int rB = lj + ((sel >> 1) << 3);
    const int rV = lj + ((sel & 1) << 3);

    const uint32_t aQ0 = sb + SM_Q + (uint32_t)(m0 + rA) * 512u;
    const uint32_t aQ1 = aQ0 + 16u * 512u;
    const uint32_t aP0 = sb + SM_P + (uint32_t)(m0 + rA) * 256u;
    const uint32_t aP1 = aP0 + 16u * 256u;
    const uint32_t bK0 = sb + SM_KV + (uint32_t)(n0s + rB) * 512u;
    const uint32_t bK1 = bK0 + 16u * 512u;
    const uint32_t pr0 = sb + SM_P + (uint32_t)(m0 + g) * 256u;

    // ---- load Q tile (64 x 256): scale = (1/16)*log2(e) folded ----
    {
        const float s = 0.0625f * 1.44269504f;
        const float4* gq = reinterpret_cast<const float4*>(q + ((size_t)(b * 1024 + q0)) * 256);
        #pragma unroll
        for (int i = 0; i < 16; i++) {
            int idx = tid + (i << 8);            // 4096 float4
            float4 v = gq[idx];
            int r = idx >> 6;
            uint32_t c2 = (uint32_t)(idx & 63) << 3;
            uint32_t ad = sb + SM_Q + (uint32_t)r * 512u + (c2 ^ ((uint32_t)(r & 7) << 4));
            STS64(ad, f2h2(v.x * s, v.y * s), f2h2(v.z * s, v.w * s));
        }
    }

    float oacc[64];                      // [mb*32 + dd*8 + tt*4 + i]
    #pragma unroll
    for (int i = 0; i < 64; i++) oacc[i] = 0.f;
    float rsum[4] = {0.f, 0.f, 0.f, 0.f};

    const float4* gkv = reinterpret_cast<const float4*>(kv + (size_t)b * 262144);

    for (int t = 0; t < 8; t++) {
        __syncthreads();                 // S1: PV(t-1) done -> KV buffer writable
        // ---- load KV tile t (128 x 256): 8192 float4 over 256 threads ----
        #pragma unroll
        for (int i = 0; i < 32; i++) {
            int idx = tid + (i << 8);
            float4 v = gkv[(t << 13) + idx];
            int r = idx >> 6;
            uint32_t c2 = (uint32_t)(idx & 63) << 3;
            uint32_t ad = sb + SM_KV + (uint32_t)r * 512u + (c2 ^ ((uint32_t)(r & 7) << 4));
            STS64(ad, f2h2(v.x, v.y), f2h2(v.z, v.w));
        }
        __syncthreads();                 // S2: KV visible

        // ---- S = Qs . K^T  (m32 x n32, k256) ----
        float sacc[32];                  // [mb*16 + nb*8 + tt*4 + i]
        #pragma unroll
        for (int i = 0; i < 32; i++) sacc[i] = 0.f;
        #pragma unroll
        for (int kk = 0; kk < 16; kk++) {
            const uint32_t ka = (((uint32_t)kk << 5) | colselA) ^ swl;
            const uint32_t kb = (((uint32_t)kk << 5) | colselB) ^ swl;
            uint32_t a0, a1, a2, a3, a4, a5, a6, a7;
            LDSM_X4(a0, a1, a2, a3, aQ0 + ka);
            LDSM_X4(a4, a5, a6, a7, aQ1 + ka);
            #pragma unroll
            for (int nb = 0; nb < 2; nb++) {
                uint32_t b0, b1, b2, b3;
                LDSM_X4(b0, b1, b2, b3, (nb ? bK1 : bK0) + kb);
                MMA(&sacc[nb * 8 + 0],      a0, a1, a2, a3, b0, b1);
                MMA(&sacc[nb * 8 + 4],      a0, a1, a2, a3, b2, b3);
                MMA(&sacc[16 + nb * 8 + 0], a4, a5, a6, a7, b0, b1);
                MMA(&sacc[16 + nb * 8 + 4], a4, a5, a6, a7, b2, b3);
            }
        }

        // ---- P = ex2(S) -> smem; accumulate rowsums ----
        #pragma unroll
        for (int mb = 0; mb < 2; mb++) {
            const uint32_t base = pr0 + (uint32_t)(mb << 12);   // +16 rows
            #pragma unroll
            for (int j = 0; j < 4; j++) {                        // j = nb*2 + tt
                float* c = &sacc[mb * 16 + j * 4];
                float e0 = ex2(c[0]), e1 = ex2(c[1]);
                float e2 = ex2(c[2]), e3 = ex2(c[3]);
                rsum[mb * 2]     += e0 + e1;
                rsum[mb * 2 + 1] += e2 + e3;
                uint32_t col2 = ((uint32_t)(n0s + (j << 3) + (tig << 1)) << 1);
                STS32(base + (col2 ^ gx),         f2h2(e0, e1));
                STS32(base + 2048u + (col2 ^ gx), f2h2(e2, e3));
            }
        }
        __syncthreads();                 // S3: P fully exchanged

        // ---- O += P . V  (m32 x n64, k128) ----
        #pragma unroll
        for (int kk = 0; kk < 8; kk++) {
            const uint32_t ka = (((uint32_t)kk << 5) | colselA) ^ swl;
            uint32_t a0, a1, a2, a3, a4, a5, a6, a7;
            LDSM_X4(a0, a1, a2, a3, aP0 + ka);
            LDSM_X4(a4, a5, a6, a7, aP1 + ka);
            const uint32_t vrow = sb + SM_KV + (uint32_t)((kk << 4) + rV) * 512u;
            #pragma unroll
            for (int dd = 0; dd < 4; dd++) {
                uint32_t b0, b1, b2, b3;
                uint32_t va = vrow + ((((uint32_t)(d0q + (dd << 4)) << 1) | colselA) ^ swl);
                LDSM_X4_T(b0, b1, b2, b3, va);
                MMA(&oacc[dd * 8 + 0],      a0, a1, a2, a3, b0, b1);
                MMA(&oacc[dd * 8 + 4],      a0, a1, a2, a3, b2, b3);
                MMA(&oacc[32 + dd * 8 + 0], a4, a5, a6, a7, b0, b1);
                MMA(&oacc[32 + dd * 8 + 4], a4, a5, a6, a7, b2, b3);
            }
        }
    }

    // ---- rowsums (RS aliases P: sync so all warps are done reading P) ----
    #pragma unroll
    for (int i = 0; i < 4; i++) {
        rsum[i] += __shfl_xor_sync(0xffffffffu, rsum[i], 1);
        rsum[i] += __shfl_xor_sync(0xffffffffu, rsum[i], 2);
    }
    __syncthreads();
    float* rs = reinterpret_cast<float*>(smem + SM_RS);   // [64][4]
    if (tig == 0) {
        rs[((m0 + g) << 2)      + (w & 3)] = rsum[0];
        rs[((m0 + 8 + g) << 2)  + (w & 3)] = rsum[1];
        rs[((m0 + 16 + g) << 2) + (w & 3)] = rsum[2];
        rs[((m0 + 24 + g) << 2) + (w & 3)] = rsum[3];
    }
    __syncthreads();

    // ---- normalize + store O ----
    #pragma unroll
    for (int mb = 0; mb < 2; mb++) {
        const int r0 = m0 + (mb << 4) + g;
        const float inv0 = 1.0f / (rs[(r0 << 2)] + rs[(r0 << 2) + 1] +
                                   rs[(r0 << 2) + 2] + rs[(r0 << 2) + 3]);
        const int r1 = r0 + 8;
        const float inv1 = 1.0f / (rs[(r1 << 2)] + rs[(r1 << 2) + 1] +
                                   rs[(r1 << 2) + 2] + rs[(r1 << 2) + 3]);
        float* o0 = out + ((size_t)(b * 1024 + q0 + r0)) * 256;
        float* o1 = o0 + 2048;           // +8 rows
        #pragma unroll
        for (int dd = 0; dd < 4; dd++) {
            #pragma unroll
            for (int tt = 0; tt < 2; tt++) {
                float* c = &oacc[mb * 32 + dd * 8 + tt * 4];
                int col = d0q + (dd << 4) + (tt << 3) + (tig << 1);
                float2 v0; v0.x = c[0] * inv0; v0.y = c[1] * inv0;
                float2 v1; v1.x = c[2] * inv1; v1.y = c[3] * inv1;
                *reinterpret_cast<float2*>(o0 + col) = v0;
                *reinterpret_cast<float2*>(o1 + col) = v1;
            }
        }
    }
}

extern "C" void kernel_launch(void* const* d_in, const int* in_sizes, int n_in,
                              void* d_out, int out_size) {
    const float* q  = (const float*)d_in[0];
    const float* kv = (const float*)d_in[1];
    float* out = (float*)d_out;
    cudaFuncSetAttribute(attn_kernel, cudaFuncAttributeMaxDynamicSharedMemorySize, SMEM_BYTES);
    attn_kernel<<<1024, 256, SMEM_BYTES>>>(q, kv, out);
}

// round 12
// speedup vs baseline: 1.3708x; 1.3708x over previous
#include <cuda_runtime.h>
#include <cuda_fp16.h>
#include <cstdint>
#include <cstddef>

// ---------------- SMEM layout (bytes) ----------------
// Q   : [128 rows][256 d] fp16, row stride 512B, 16B-chunk XOR swizzle -> 64KB
// KV0/KV1 : double-buffered KV tiles, same layout -> 2 x 64KB
// P   : [128 rows][128 kv] fp16, row stride 256B -> 32KB
// RS  : float[128][4] ALIASED over P (P dead after last PV)
#define SM_Q   0
#define SM_KV  65536           /* + (t&1)<<16 */
#define SM_P   196608
#define SM_RS  196608
#define SMEM_BYTES 229376

// ---------------- helpers ----------------
__device__ __forceinline__ uint32_t smem_u32(const void* p) {
    uint32_t a;
    asm("{ .reg .u64 t; cvta.to.shared.u64 t, %1; cvt.u32.u64 %0, t; }" : "=r"(a) : "l"(p));
    return a;
}
// pack two fp32 -> fp16x2, a in LOW half
__device__ __forceinline__ uint32_t f2h2(float a, float b) {
    uint32_t r;
    asm("cvt.rn.f16x2.f32 %0, %2, %1;" : "=r"(r) : "f"(a), "f"(b));
    return r;
}
__device__ __forceinline__ float ex2(float x) {
    float r;
    asm("ex2.approx.f32 %0, %1;" : "=f"(r) : "f"(x));
    return r;
}

#define STS32(addr, v) \
    asm volatile("st.shared.b32 [%0], %1;" :: "r"(addr), "r"(v) : "memory")
#define STS64(addr, v0, v1) \
    asm volatile("st.shared.v2.b32 [%0], {%1, %2};" :: "r"(addr), "r"(v0), "r"(v1) : "memory")

#define LDSM_X4(r0, r1, r2, r3, addr)                                          \
    asm volatile("ldmatrix.sync.aligned.m8n8.x4.shared.b16 {%0,%1,%2,%3}, [%4];" \
        : "=r"(r0), "=r"(r1), "=r"(r2), "=r"(r3) : "r"(addr))
#define LDSM_X4_T(r0, r1, r2, r3, addr)                                        \
    asm volatile("ldmatrix.sync.aligned.m8n8.x4.trans.shared.b16 {%0,%1,%2,%3}, [%4];" \
        : "=r"(r0), "=r"(r1), "=r"(r2), "=r"(r3) : "r"(addr))

// D(f32x4) += A(f16, m16k16) * B(f16, k16n8)
#define MMA(c, a0, a1, a2, a3, b0, b1)                                         \
    asm volatile("mma.sync.aligned.m16n8k16.row.col.f32.f16.f16.f32 "          \
        "{%0,%1,%2,%3},{%4,%5,%6,%7},{%8,%9},{%0,%1,%2,%3};"                   \
        : "+f"((c)[0]), "+f"((c)[1]), "+f"((c)[2]), "+f"((c)[3])               \
        : "r"(a0), "r"(a1), "r"(a2), "r"(a3), "r"(b0), "r"(b1))

// ---------------- kernel ----------------
// grid 512 = 64 batches x 8 q-tiles of 128 rows; block 512 = 16 warps; 1 CTA/SM.
// S  phase: warp w -> rows [32*(w>>2), +32), kv cols [32*(w&3), +32)   (m32 x n32)
// PV phase: warp w -> rows [32*(w>>2), +32), d  cols [64*(w&3), +64)   (m32 x n64)
// KV double-buffered in smem; tile t+1 LDG+STS issued after exp(t) (sacc dead,
// no long register lifetimes), hidden behind barrier B + PV(t). 2 syncs/tile.
__global__ void __launch_bounds__(512, 1)
attn_kernel(const float* __restrict__ q, const float* __restrict__ kv,
            float* __restrict__ out)
{
    extern __shared__ __align__(16) char smem[];
    const uint32_t sb = smem_u32(smem);
    const int tid  = threadIdx.x;
    const int lane = tid & 31, w = tid >> 5;
    const int b  = blockIdx.x >> 3;
    const int q0 = (blockIdx.x & 7) << 7;
    const int g = lane >> 2, tig = lane & 3;
    const int lj = lane & 7, sel = lane >> 3;
    const uint32_t swl = (uint32_t)lj << 4;
    const uint32_t gx  = (uint32_t)g << 4;

    const int m0  = (w >> 2) << 5;      // row base (both phases)
    const int n0s = (w & 3) << 5;       // S kv-quarter base
    const int d0q = (w & 3) << 6;       // PV d-quarter base

    // fragment lane geometry (validated R8-R11)
    const uint32_t colselA = (uint32_t)(sel >> 1) << 4;  // A-type and V-trans
    const uint32_t colselB = (uint32_t)(sel & 1) << 4;   // B-type non-trans
    const int rA = lj + ((sel & 1) << 3);
    const int rB = lj + ((sel >> 1) << 3);
    const int rV = lj + ((sel & 1) << 3);

    const uint32_t aQ0 = sb + SM_Q + (uint32_t)(m0 + rA) * 512u;
    const uint32_t aQ1 = aQ0 + 16u * 512u;
    const uint32_t aP0 = sb + SM_P + (uint32_t)(m0 + rA) * 256u;
    const uint32_t aP1 = aP0 + 16u * 256u;
    const uint32_t pr0 = sb + SM_P + (uint32_t)(m0 + g) * 256u;

    // ---- load Q tile: scale = (1/16)*log2(e) folded so P = ex2(S) ----
    {
        const float s = 0.0625f * 1.44269504f;
        const float4* gq = reinterpret_cast<const float4*>(q + ((size_t)(b * 1024 + q0)) * 256);
        #pragma unroll
        for (int i = 0; i < 16; i++) {
            int idx = tid + (i << 9);
            float4 v = gq[idx];
            int r = idx >> 6;
            uint32_t c2 = (uint32_t)(idx & 63) << 3;
            uint32_t ad = sb + SM_Q + (uint32_t)r * 512u + (c2 ^ ((uint32_t)(r & 7) << 4));
            STS64(ad, f2h2(v.x * s, v.y * s), f2h2(v.z * s, v.w * s));
        }
    }

    const float4* gkv = reinterpret_cast<const float4*>(kv + (size_t)b * 262144);

    // ---- prologue: KV tile 0 -> buffer 0 ----
    #pragma unroll
    for (int i = 0; i < 16; i++) {
        int idx = tid + (i << 9);
        float4 v = gkv[idx];
        int r = idx >> 6;
        uint32_t c2 = (uint32_t)(idx & 63) << 3;
        uint32_t ad = sb + SM_KV + (uint32_t)r * 512u + (c2 ^ ((uint32_t)(r & 7) << 4));
        STS64(ad, f2h2(v.x, v.y), f2h2(v.z, v.w));
    }

    float oacc[64];                      // [mb*32 + dd*8 + tt*4 + i]
    #pragma unroll
    for (int i = 0; i < 64; i++) oacc[i] = 0.f;
    float rsum[4] = {0.f, 0.f, 0.f, 0.f};

    __syncthreads();                     // Q + KV0 visible

    for (int t = 0; t < 8; t++) {
        const uint32_t kvb = sb + SM_KV + (uint32_t)((t & 1) << 16);
        const uint32_t bK0 = kvb + (uint32_t)(n0s + rB) * 512u;
        const uint32_t bK1 = bK0 + 16u * 512u;

        // ---- S = Qs . K^T  (m32 x n32, k256) ----
        float sacc[32];                  // [mb*16 + nb*8 + tt*4 + i]
        #pragma unroll
        for (int i = 0; i < 32; i++) sacc[i] = 0.f;
        #pragma unroll
        for (int kk = 0; kk < 16; kk++) {
            const uint32_t ka = (((uint32_t)kk << 5) | colselA) ^ swl;
            const uint32_t kb = (((uint32_t)kk << 5) | colselB) ^ swl;
            uint32_t a0, a1, a2, a3, a4, a5, a6, a7;
            LDSM_X4(a0, a1, a2, a3, aQ0 + ka);
            LDSM_X4(a4, a5, a6, a7, aQ1 + ka);
            #pragma unroll
            for (int nb = 0; nb < 2; nb++) {
                uint32_t b0, b1, b2, b3;
                LDSM_X4(b0, b1, b2, b3, (nb ? bK1 : bK0) + kb);
                MMA(&sacc[nb * 8 + 0],      a0, a1, a2, a3, b0, b1);
                MMA(&sacc[nb * 8 + 4],      a0, a1, a2, a3, b2, b3);
                MMA(&sacc[16 + nb * 8 + 0], a4, a5, a6, a7, b0, b1);
                MMA(&sacc[16 + nb * 8 + 4], a4, a5, a6, a7, b2, b3);
            }
        }

        // ---- P = ex2(S) -> smem; accumulate rowsums (sacc dies here) ----
        #pragma unroll
        for (int mb = 0; mb < 2; mb++) {
            const uint32_t base = pr0 + (uint32_t)(mb << 12);   // +16 rows
            #pragma unroll
            for (int j = 0; j < 4; j++) {                        // j = nb*2 + tt
                float* c = &sacc[mb * 16 + j * 4];
                float e0 = ex2(c[0]), e1 = ex2(c[1]);
                float e2 = ex2(c[2]), e3 = ex2(c[3]);
                rsum[mb * 2]     += e0 + e1;
                rsum[mb * 2 + 1] += e2 + e3;
                uint32_t col2 = ((uint32_t)(n0s + (j << 3) + (tig << 1)) << 1);
                STS32(base + (col2 ^ gx),         f2h2(e0, e1));
                STS32(base + 2048u + (col2 ^ gx), f2h2(e2, e3));
            }
        }

        // ---- prefetch KV tile t+1 -> other buffer (no barrier before PV) ----
        if (t < 7) {
            const uint32_t nb2 = sb + SM_KV + (uint32_t)((~t & 1) << 16);
            #pragma unroll
            for (int i = 0; i < 16; i++) {
                int idx = tid + (i << 9);
                float4 v = gkv[((t + 1) << 13) + idx];
                int r = idx >> 6;
                uint32_t c2 = (uint32_t)(idx & 63) << 3;
                uint32_t ad = nb2 + (uint32_t)r * 512u + (c2 ^ ((uint32_t)(r & 7) << 4));
                STS64(ad, f2h2(v.x, v.y), f2h2(v.z, v.w));
            }
        }
        __syncthreads();                 // B: P(t) visible (KV(t+1) rides along)

        // ---- O += P . V  (m32 x n64, k128), V from buf[t&1] ----
        #pragma unroll
        for (int kk = 0; kk < 8; kk++) {
            const uint32_t ka = (((uint32_t)kk << 5) | colselA) ^ swl;
            uint32_t a0, a1, a2, a3, a4, a5, a6, a7;
            LDSM_X4(a0, a1, a2, a3, aP0 + ka);
            LDSM_X4(a4, a5, a6, a7, aP1 + ka);
            const uint32_t vrow = kvb + (uint32_t)((kk << 4) + rV) * 512u;
            #pragma unroll
            for (int dd = 0; dd < 4; dd++) {
                uint32_t b0, b1, b2, b3;
                uint32_t va = vrow + ((((uint32_t)(d0q + (dd << 4)) << 1) | colselA) ^ swl);
                LDSM_X4_T(b0, b1, b2, b3, va);
                MMA(&oacc[dd * 8 + 0],      a0, a1, a2, a3, b0, b1);
                MMA(&oacc[dd * 8 + 4],      a0, a1, a2, a3, b2, b3);
                MMA(&oacc[32 + dd * 8 + 0], a4, a5, a6, a7, b0, b1);
                MMA(&oacc[32 + dd * 8 + 4], a4, a5, a6, a7, b2, b3);
            }
        }
        __syncthreads();                 // A: PV(t) done -> P & old KV buffer writable
    }

    // ---- rowsums (RS aliases P; last barrier A guarantees P dead) ----
    #pragma unroll
    for (int i = 0; i < 4; i++) {
        rsum[i] += __shfl_xor_sync(0xffffffffu, rsum[i], 1);
        rsum[i] += __shfl_xor_sync(0xffffffffu, rsum[i], 2);
    }
    float* rs = reinterpret_cast<float*>(smem + SM_RS);   // [128][4]
    if (tig == 0) {
        rs[((m0 + g) << 2)      + (w & 3)] = rsum[0];
        rs[((m0 + 8 + g) << 2)  + (w & 3)] = rsum[1];
        rs[((m0 + 16 + g) << 2) + (w & 3)] = rsum[2];
        rs[((m0 + 24 + g) << 2) + (w & 3)] = rsum[3];
    }
    __syncthreads();

    // ---- normalize + store O ----
    #pragma unroll
    for (int mb = 0; mb < 2; mb++) {
        const int r0 = m0 + (mb << 4) + g;
        const float inv0 = 1.0f / (rs[(r0 << 2)] + rs[(r0 << 2) + 1] +
                                   rs[(r0 << 2) + 2] + rs[(r0 << 2) + 3]);
        const int r1 = r0 + 8;
        const float inv1 = 1.0f / (rs[(r1 << 2)] + rs[(r1 << 2) + 1] +
                                   rs[(r1 << 2) + 2] + rs[(r1 << 2) + 3]);
        float* o0 = out + ((size_t)(b * 1024 + q0 + r0)) * 256;
        float* o1 = o0 + 2048;           // +8 rows
        #pragma unroll
        for (int dd = 0; dd < 4; dd++) {
            #pragma unroll
            for (int tt = 0; tt < 2; tt++) {
                float* c = &oacc[mb * 32 + dd * 8 + tt * 4];
                int col = d0q + (dd << 4) + (tt << 3) + (tig << 1);
                float2 v0; v0.x = c[0] * inv0; v0.y = c[1] * inv0;
                float2 v1; v1.x = c[2] * inv1; v1.y = c[3] * inv1;
                *reinterpret_cast<float2*>(o0 + col) = v0;
                *reinterpret_cast<float2*>(o1 + col) = v1;
            }
        }
    }
}

extern "C" void kernel_launch(void* const* d_in, const int* in_sizes, int n_in,
                              void* d_out, int out_size) {
    const float* q  = (const float*)d_in[0];
    const float* kv = (const float*)d_in[1];
    float* out = (float*)d_out;
    cudaFuncSetAttribute(attn_kernel, cudaFuncAttributeMaxDynamicSharedMemorySize, SMEM_BYTES);
    attn_kernel<<<512, 512, SMEM_BYTES>>>(q, kv, out);
}

// round 13
// speedup vs baseline: 1.7230x; 1.2569x over previous
#include <cuda_runtime.h>
#include <cuda_fp16.h>
#include <cstdint>
#include <cstddef>

// ---------------- global fp16 KV scratch (pre-converted, pre-swizzled) ----------------
// Layout: [b][t] tile images of 65536B, each byte-identical to the smem KV buffer:
//   offset(r, k16) = r*512 + ((k16*16) ^ ((r&7)*16)),  r in [0,128), k16 in [0,32)
#define KV16_BYTES (64u * 8u * 65536u)   // 32 MB
__device__ __align__(16) unsigned char g_kv16[KV16_BYTES];

// ---------------- SMEM layout (bytes) ----------------
// Q   : [128 rows][256 d] fp16, row stride 512B, 16B-chunk XOR swizzle -> 64KB
// KV0/KV1 : double-buffered KV tile images -> 2 x 64KB (filled by cp.async)
// P   : [128 rows][128 kv] fp16, row stride 256B -> 32KB
// RS  : float[128][4] ALIASED over P (P dead after last PV)
#define SM_Q   0
#define SM_KV  65536           /* + (t&1)<<16 */
#define SM_P   196608
#define SM_RS  196608
#define SMEM_BYTES 229376

// ---------------- helpers ----------------
__device__ __forceinline__ uint32_t smem_u32(const void* p) {
    uint32_t a;
    asm("{ .reg .u64 t; cvta.to.shared.u64 t, %1; cvt.u32.u64 %0, t; }" : "=r"(a) : "l"(p));
    return a;
}
// pack two fp32 -> fp16x2, a in LOW half
__device__ __forceinline__ uint32_t f2h2(float a, float b) {
    uint32_t r;
    asm("cvt.rn.f16x2.f32 %0, %2, %1;" : "=r"(r) : "f"(a), "f"(b));
    return r;
}
__device__ __forceinline__ float ex2(float x) {
    float r;
    asm("ex2.approx.f32 %0, %1;" : "=f"(r) : "f"(x));
    return r;
}

#define STS32(addr, v) \
    asm volatile("st.shared.b32 [%0], %1;" :: "r"(addr), "r"(v) : "memory")
#define STS64(addr, v0, v1) \
    asm volatile("st.shared.v2.b32 [%0], {%1, %2};" :: "r"(addr), "r"(v0), "r"(v1) : "memory")

#define CP_ASYNC16(dst, src) \
    asm volatile("cp.async.cg.shared.global [%0], [%1], 16;" :: "r"(dst), "l"(src) : "memory")
#define CP_COMMIT()  asm volatile("cp.async.commit_group;" ::: "memory")
#define CP_WAIT1()   asm volatile("cp.async.wait_group 1;" ::: "memory")

#define LDSM_X4(r0, r1, r2, r3, addr)                                          \
    asm volatile("ldmatrix.sync.aligned.m8n8.x4.shared.b16 {%0,%1,%2,%3}, [%4];" \
        : "=r"(r0), "=r"(r1), "=r"(r2), "=r"(r3) : "r"(addr))
#define LDSM_X4_T(r0, r1, r2, r3, addr)                                        \
    asm volatile("ldmatrix.sync.aligned.m8n8.x4.trans.shared.b16 {%0,%1,%2,%3}, [%4];" \
        : "=r"(r0), "=r"(r1), "=r"(r2), "=r"(r3) : "r"(addr))

// D(f32x4) += A(f16, m16k16) * B(f16, k16n8)
#define MMA(c, a0, a1, a2, a3, b0, b1)                                         \
    asm volatile("mma.sync.aligned.m16n8k16.row.col.f32.f16.f16.f32 "          \
        "{%0,%1,%2,%3},{%4,%5,%6,%7},{%8,%9},{%0,%1,%2,%3};"                   \
        : "+f"((c)[0]), "+f"((c)[1]), "+f"((c)[2]), "+f"((c)[3])               \
        : "r"(a0), "r"(a1), "r"(a2), "r"(a3), "r"(b0), "r"(b1))

// ---------------- pre-pass: fp32 KV -> fp16 swizzled tile images ----------------
// 2,097,152 16B-chunks total; 1 chunk per thread; grid 4096 x 512.
__global__ void __launch_bounds__(512, 4)
cvt_kv_kernel(const float* __restrict__ kv)
{
    uint32_t cid = blockIdx.x * 512u + threadIdx.x;
    uint32_t j  = cid & 4095u;           // chunk within tile
    uint32_t bt = cid >> 12;             // b*8 + t
    uint32_t r = j >> 5, k = j & 31u;
    uint32_t b = bt >> 3, t = bt & 7u;
    size_t fbase = (size_t)b * 262144 + (size_t)(t * 128u + r) * 256 + (size_t)(k * 8u);
    float4 v0 = *reinterpret_cast<const float4*>(kv + fbase);
    float4 v1 = *reinterpret_cast<const float4*>(kv + fbase + 4);
    uint4 o;
    o.x = f2h2(v0.x, v0.y); o.y = f2h2(v0.z, v0.w);
    o.z = f2h2(v1.x, v1.y); o.w = f2h2(v1.z, v1.w);
    uint32_t doff = (bt << 16) + r * 512u + ((k << 4) ^ ((r & 7u) << 4));
    *reinterpret_cast<uint4*>(g_kv16 + doff) = o;
}

// ---------------- main kernel ----------------
// grid 512 = 64 batches x 8 q-tiles of 128 rows; block 512 = 16 warps; 1 CTA/SM.
// S  phase: warp w -> rows [32*(w>>2), +32), kv cols [32*(w&3), +32)   (m32 x n32)
// PV phase: warp w -> rows [32*(w>>2), +32), d  cols [64*(w&3), +64)   (m32 x n64)
// KV arrives via 2-deep cp.async pipeline from g_kv16 (tile t+2 issued after PV(t)).
__global__ void __launch_bounds__(512, 1)
attn_kernel(const float* __restrict__ q, float* __restrict__ out)
{
    extern __shared__ __align__(16) char smem[];
    const uint32_t sb = smem_u32(smem);
    const int tid  = threadIdx.x;
    const int lane = tid & 31, w = tid >> 5;
    const int b  = blockIdx.x >> 3;
    const int q0 = (blockIdx.x & 7) << 7;
    const int g = lane >> 2, tig = lane & 3;
    const int lj = lane & 7, sel = lane >> 3;
    const uint32_t swl = (uint32_t)lj << 4;
    const uint32_t gx  = (uint32_t)g << 4;

    const int m0  = (w >> 2) << 5;      // row base (both phases)
    const int n0s = (w & 3) << 5;       // S kv-quarter base
    const int d0q = (w & 3) << 6;       // PV d-quarter base

    // fragment lane geometry (validated R8-R12)
    const uint32_t colselA = (uint32_t)(sel >> 1) << 4;  // A-type and V-trans
    const uint32_t colselB = (uint32_t)(sel & 1) << 4;   // B-type non-trans
    const int rA = lj + ((sel & 1) << 3);
    const int rB = lj + ((sel >> 1) << 3);
    const int rV = lj + ((sel & 1) << 3);

    const uint32_t aQ0 = sb + SM_Q + (uint32_t)(m0 + rA) * 512u;
    const uint32_t aQ1 = aQ0 + 16u * 512u;
    const uint32_t aP0 = sb + SM_P + (uint32_t)(m0 + rA) * 256u;
    const uint32_t aP1 = aP0 + 16u * 256u;
    const uint32_t pr0 = sb + SM_P + (uint32_t)(m0 + g) * 256u;

    const unsigned char* kvsrc = g_kv16 + ((size_t)(b << 3) << 16);

    // ---- prologue: issue cp.async for KV tiles 0 and 1 ----
    {
        const uint32_t off0 = (uint32_t)tid << 4;
        #pragma unroll
        for (int i = 0; i < 8; i++) {
            uint32_t off = off0 + ((uint32_t)i << 13);
            CP_ASYNC16(sb + SM_KV + off, kvsrc + off);
        }
        CP_COMMIT();
        #pragma unroll
        for (int i = 0; i < 8; i++) {
            uint32_t off = off0 + ((uint32_t)i << 13);
            CP_ASYNC16(sb + SM_KV + 65536u + off, kvsrc + 65536u + off);
        }
        CP_COMMIT();
    }

    // ---- load Q tile: scale = (1/16)*log2(e) folded so P = ex2(S) ----
    {
        const float s = 0.0625f * 1.44269504f;
        const float4* gq = reinterpret_cast<const float4*>(q + ((size_t)(b * 1024 + q0)) * 256);
        #pragma unroll
        for (int i = 0; i < 16; i++) {
            int idx = tid + (i << 9);
            float4 v = gq[idx];
            int r = idx >> 6;
            uint32_t c2 = (uint32_t)(idx & 63) << 3;
            uint32_t ad = sb + SM_Q + (uint32_t)r * 512u + (c2 ^ ((uint32_t)(r & 7) << 4));
            STS64(ad, f2h2(v.x * s, v.y * s), f2h2(v.z * s, v.w * s));
        }
    }

    float oacc[64];                      // [mb*32 + dd*8 + tt*4 + i]
    #pragma unroll
    for (int i = 0; i < 64; i++) oacc[i] = 0.f;
    float rsum[4] = {0.f, 0.f, 0.f, 0.f};

    for (int t = 0; t < 8; t++) {
        CP_WAIT1();                      // this thread's tile-t chunks landed
        __syncthreads();                 // S1: all threads' chunks + PV(t-1) done

        const uint32_t kvb = sb + SM_KV + (uint32_t)((t & 1) << 16);
        const uint32_t bK0 = kvb + (uint32_t)(n0s + rB) * 512u;
        const uint32_t bK1 = bK0 + 16u * 512u;

        // ---- S = Qs . K^T  (m32 x n32, k256) ----
        float sacc[32];                  // [mb*16 + nb*8 + tt*4 + i]
        #pragma unroll
        for (int i = 0; i < 32; i++) sacc[i] = 0.f;
        #pragma unroll
        for (int kk = 0; kk < 16; kk++) {
            const uint32_t ka = (((uint32_t)kk << 5) | colselA) ^ swl;
            const uint32_t kb = (((uint32_t)kk << 5) | colselB) ^ swl;
            uint32_t a0, a1, a2, a3, a4, a5, a6, a7;
            LDSM_X4(a0, a1, a2, a3, aQ0 + ka);
            LDSM_X4(a4, a5, a6, a7, aQ1 + ka);
            #pragma unroll
            for (int nb = 0; nb < 2; nb++) {
                uint32_t b0, b1, b2, b3;
                LDSM_X4(b0, b1, b2, b3, (nb ? bK1 : bK0) + kb);
                MMA(&sacc[nb * 8 + 0],      a0, a1, a2, a3, b0, b1);
                MMA(&sacc[nb * 8 + 4],      a0, a1, a2, a3, b2, b3);
                MMA(&sacc[16 + nb * 8 + 0], a4, a5, a6, a7, b0, b1);
                MMA(&sacc[16 + nb * 8 + 4], a4, a5, a6, a7, b2, b3);
            }
        }

        // ---- P = ex2(S) -> smem; accumulate rowsums ----
        #pragma unroll
        for (int mb = 0; mb < 2; mb++) {
            const uint32_t base = pr0 + (uint32_t)(mb << 12);   // +16 rows
            #pragma unroll
            for (int j = 0; j < 4; j++) {                        // j = nb*2 + tt
                float* c = &sacc[mb * 16 + j * 4];
                float e0 = ex2(c[0]), e1 = ex2(c[1]);
                float e2 = ex2(c[2]), e3 = ex2(c[3]);
                rsum[mb * 2]     += e0 + e1;
                rsum[mb * 2 + 1] += e2 + e3;
                uint32_t col2 = ((uint32_t)(n0s + (j << 3) + (tig << 1)) << 1);
                STS32(base + (col2 ^ gx),         f2h2(e0, e1));
                STS32(base + 2048u + (col2 ^ gx), f2h2(e2, e3));
            }
        }
        __syncthreads();                 // S2: P fully exchanged

        // ---- O += P . V  (m32 x n64, k128), V from buf[t&1] ----
        #pragma unroll
        for (int kk = 0; kk < 8; kk++) {
            const uint32_t ka = (((uint32_t)kk << 5) | colselA) ^ swl;
            uint32_t a0, a1, a2, a3, a4, a5, a6, a7;
            LDSM_X4(a0, a1, a2, a3, aP0 + ka);
            LDSM_X4(a4, a5, a6, a7, aP1 + ka);
            const uint32_t vrow = kvb + (uint32_t)((kk << 4) + rV) * 512u;
            #pragma unroll
            for (int dd = 0; dd < 4; dd++) {
                uint32_t b0, b1, b2, b3;
                uint32_t va = vrow + ((((uint32_t)(d0q + (dd << 4)) << 1) | colselA) ^ swl);
                LDSM_X4_T(b0, b1, b2, b3, va);
                MMA(&oacc[dd * 8 + 0],      a0, a1, a2, a3, b0, b1);
                MMA(&oacc[dd * 8 + 4],      a0, a1, a2, a3, b2, b3);
                MMA(&oacc[32 + dd * 8 + 0], a4, a5, a6, a7, b0, b1);
                MMA(&oacc[32 + dd * 8 + 4], a4, a5, a6, a7, b2, b3);
            }
        }
        __syncthreads();                 // S3: PV(t) done -> buf[t&1] free, P free

        // ---- issue cp.async for tile t+2 into the freed buffer ----
        if (t < 6) {
            const unsigned char* src = kvsrc + ((uint32_t)(t + 2) << 16);
            const uint32_t dstb = sb + SM_KV + (uint32_t)((t & 1) << 16);
            const uint32_t off0 = (uint32_t)tid << 4;
            #pragma unroll
            for (int i = 0; i < 8; i++) {
                uint32_t off = off0 + ((uint32_t)i << 13);
                CP_ASYNC16(dstb + off, src + off);
            }
        }
        CP_COMMIT();                     // empty groups for t>=6 keep wait count uniform
    }

    // ---- rowsums (RS aliases P; final S3 guarantees P dead) ----
    #pragma unroll
    for (int i = 0; i < 4; i++) {
        rsum[i] += __shfl_xor_sync(0xffffffffu, rsum[i], 1);
        rsum[i] += __shfl_xor_sync(0xffffffffu, rsum[i], 2);
    }
    float* rs = reinterpret_cast<float*>(smem + SM_RS);   // [128][4]
    if (tig == 0) {
        rs[((m0 + g) << 2)      + (w & 3)] = rsum[0];
        rs[((m0 + 8 + g) << 2)  + (w & 3)] = rsum[1];
        rs[((m0 + 16 + g) << 2) + (w & 3)] = rsum[2];
        rs[((m0 + 24 + g) << 2) + (w & 3)] = rsum[3];
    }
    __syncthreads();

    // ---- normalize + store O ----
    #pragma unroll
    for (int mb = 0; mb < 2; mb++) {
        const int r0 = m0 + (mb << 4) + g;
        const float inv0 = 1.0f / (rs[(r0 << 2)] + rs[(r0 << 2) + 1] +
                                   rs[(r0 << 2) + 2] + rs[(r0 << 2) + 3]);
        const int r1 = r0 + 8;
        const float inv1 = 1.0f / (rs[(r1 << 2)] + rs[(r1 << 2) + 1] +
                                   rs[(r1 << 2) + 2] + rs[(r1 << 2) + 3]);
        float* o0 = out + ((size_t)(b * 1024 + q0 + r0)) * 256;
        float* o1 = o0 + 2048;           // +8 rows
        #pragma unroll
        for (int dd = 0; dd < 4; dd++) {
            #pragma unroll
            for (int tt = 0; tt < 2; tt++) {
                float* c = &oacc[mb * 32 + dd * 8 + tt * 4];
                int col = d0q + (dd << 4) + (tt << 3) + (tig << 1);
                float2 v0; v0.x = c[0] * inv0; v0.y = c[1] * inv0;
                float2 v1; v1.x = c[2] * inv1; v1.y = c[3] * inv1;
                *reinterpret_cast<float2*>(o0 + col) = v0;
                *reinterpret_cast<float2*>(o1 + col) = v1;
            }
        }
    }
}

extern "C" void kernel_launch(void* const* d_in, const int* in_sizes, int n_in,
                              void* d_out, int out_size) {
    const float* q  = (const float*)d_in[0];
    const float* kv = (const float*)d_in[1];
    float* out = (float*)d_out;
    cvt_kv_kernel<<<4096, 512>>>(kv);
    cudaFuncSetAttribute(attn_kernel, cudaFuncAttributeMaxDynamicSharedMemorySize, SMEM_BYTES);
    attn_kernel<<<512, 512, SMEM_BYTES>>>(q, out);
}

// round 14
// speedup vs baseline: 1.8769x; 1.0893x over previous
#include <cuda_runtime.h>
#include <cuda_fp16.h>
#include <cstdint>
#include <cstddef>

// ---------------- global fp16 KV scratch (pre-converted, pre-swizzled) ----------------
// Layout: [b][t] tile images of 65536B, byte-identical to the smem KV buffer:
//   offset(r, k16) = r*512 + ((k16*16) ^ ((r&7)*16)),  r in [0,128), k16 in [0,32)
#define KV16_BYTES (64u * 8u * 65536u)   // 32 MB
__device__ __align__(16) unsigned char g_kv16[KV16_BYTES];

// ---------------- SMEM layout (bytes) ----------------
// Q  : [64 rows][256 d] fp16, row stride 512B, 16B-chunk XOR swizzle -> 32KB
// KV : single-buffered KV tile image -> 64KB (filled by cp.async; co-CTA hides latency)
// P  : [64 rows][128 kv] fp16, row stride 256B -> 16KB
// RS : float[64][4] ALIASED over P (P dead after last PV)
#define SM_Q   0
#define SM_KV  32768
#define SM_P   98304
#define SM_RS  98304
#define SMEM_BYTES 114688

// ---------------- helpers ----------------
__device__ __forceinline__ uint32_t smem_u32(const void* p) {
    uint32_t a;
    asm("{ .reg .u64 t; cvta.to.shared.u64 t, %1; cvt.u32.u64 %0, t; }" : "=r"(a) : "l"(p));
    return a;
}
// pack two fp32 -> fp16x2, a in LOW half
__device__ __forceinline__ uint32_t f2h2(float a, float b) {
    uint32_t r;
    asm("cvt.rn.f16x2.f32 %0, %2, %1;" : "=r"(r) : "f"(a), "f"(b));
    return r;
}
__device__ __forceinline__ float ex2(float x) {
    float r;
    asm("ex2.approx.f32 %0, %1;" : "=f"(r) : "f"(x));
    return r;
}

#define STS32(addr, v) \
    asm volatile("st.shared.b32 [%0], %1;" :: "r"(addr), "r"(v) : "memory")
#define STS64(addr, v0, v1) \
    asm volatile("st.shared.v2.b32 [%0], {%1, %2};" :: "r"(addr), "r"(v0), "r"(v1) : "memory")

#define CP_ASYNC16(dst, src) \
    asm volatile("cp.async.cg.shared.global [%0], [%1], 16;" :: "r"(dst), "l"(src) : "memory")
#define CP_COMMIT()  asm volatile("cp.async.commit_group;" ::: "memory")
#define CP_WAIT0()   asm volatile("cp.async.wait_group 0;" ::: "memory")

#define LDSM_X4(r0, r1, r2, r3, addr)                                          \
    asm volatile("ldmatrix.sync.aligned.m8n8.x4.shared.b16 {%0,%1,%2,%3}, [%4];" \
        : "=r"(r0), "=r"(r1), "=r"(r2), "=r"(r3) : "r"(addr))
#define LDSM_X4_T(r0, r1, r2, r3, addr)                                        \
    asm volatile("ldmatrix.sync.aligned.m8n8.x4.trans.shared.b16 {%0,%1,%2,%3}, [%4];" \
        : "=r"(r0), "=r"(r1), "=r"(r2), "=r"(r3) : "r"(addr))

// D(f32x4) += A(f16, m16k16) * B(f16, k16n8)
#define MMA(c, a0, a1, a2, a3, b0, b1)                                         \
    asm volatile("mma.sync.aligned.m16n8k16.row.col.f32.f16.f16.f32 "          \
        "{%0,%1,%2,%3},{%4,%5,%6,%7},{%8,%9},{%0,%1,%2,%3};"                   \
        : "+f"((c)[0]), "+f"((c)[1]), "+f"((c)[2]), "+f"((c)[3])               \
        : "r"(a0), "r"(a1), "r"(a2), "r"(a3), "r"(b0), "r"(b1))

// ---------------- pre-pass: fp32 KV -> fp16 swizzled tile images ----------------
__global__ void __launch_bounds__(512, 4)
cvt_kv_kernel(const float* __restrict__ kv)
{
    uint32_t cid = blockIdx.x * 512u + threadIdx.x;
    uint32_t j  = cid & 4095u;           // chunk within tile
    uint32_t bt = cid >> 12;             // b*8 + t
    uint32_t r = j >> 5, k = j & 31u;
    uint32_t b = bt >> 3, t = bt & 7u;
    size_t fbase = (size_t)b * 262144 + (size_t)(t * 128u + r) * 256 + (size_t)(k * 8u);
    float4 v0 = *reinterpret_cast<const float4*>(kv + fbase);
    float4 v1 = *reinterpret_cast<const float4*>(kv + fbase + 4);
    uint4 o;
    o.x = f2h2(v0.x, v0.y); o.y = f2h2(v0.z, v0.w);
    o.z = f2h2(v1.x, v1.y); o.w = f2h2(v1.z, v1.w);
    uint32_t doff = (bt << 16) + r * 512u + ((k << 4) ^ ((r & 7u) << 4));
    *reinterpret_cast<uint4*>(g_kv16 + doff) = o;
}

// ---------------- main kernel ----------------
// grid 1024 = 64 batches x 16 q-tiles of 64 rows; block 256 = 8 warps; 2 CTAs/SM.
// S  phase: warp w -> rows [32*(w>>2), +32), kv cols [32*(w&3), +32)   (m32 x n32)
// PV phase: warp w -> rows [32*(w>>2), +32), d  cols [64*(w&3), +64)   (m32 x n64)
// Single KV buffer: tile t+1 cp.async issued after PV(t); the exposed copy wait
// and all barrier/exp bubbles are covered by the co-resident CTA.
__global__ void __launch_bounds__(256, 2)
attn_kernel(const float* __restrict__ q, float* __restrict__ out)
{
    extern __shared__ __align__(16) char smem[];
    const uint32_t sb = smem_u32(smem);
    const int tid  = threadIdx.x;
    const int lane = tid & 31, w = tid >> 5;
    const int b  = blockIdx.x >> 4;
    const int q0 = (blockIdx.x & 15) << 6;
    const int g = lane >> 2, tig = lane & 3;
    const int lj = lane & 7, sel = lane >> 3;
    const uint32_t swl = (uint32_t)lj << 4;
    const uint32_t gx  = (uint32_t)g << 4;

    const int m0  = (w >> 2) << 5;      // row base: 0 or 32
    const int n0s = (w & 3) << 5;       // S kv-quarter base
    const int d0q = (w & 3) << 6;       // PV d-quarter base

    // fragment lane geometry (validated R8-R13)
    const uint32_t colselA = (uint32_t)(sel >> 1) << 4;  // A-type and V-trans
    const uint32_t colselB = (uint32_t)(sel & 1) << 4;   // B-type non-trans
    const int rA = lj + ((sel & 1) << 3);
    const int rB = lj + ((sel >> 1) << 3);
    const int rV = lj + ((sel & 1) << 3);

    const uint32_t aQ0 = sb + SM_Q + (uint32_t)(m0 + rA) * 512u;
    const uint32_t aQ1 = aQ0 + 16u * 512u;
    const uint32_t aP0 = sb + SM_P + (uint32_t)(m0 + rA) * 256u;
    const uint32_t aP1 = aP0 + 16u * 256u;
    const uint32_t bK0 = sb + SM_KV + (uint32_t)(n0s + rB) * 512u;
    const uint32_t bK1 = bK0 + 16u * 512u;
    const uint32_t pr0 = sb + SM_P + (uint32_t)(m0 + g) * 256u;

    const unsigned char* kvsrc = g_kv16 + ((size_t)(b << 3) << 16);

    // ---- prologue: issue cp.async for KV tile 0 (64KB over 256 threads) ----
    {
        const uint32_t off0 = (uint32_t)tid << 4;
        #pragma unroll
        for (int i = 0; i < 16; i++) {
            uint32_t off = off0 + ((uint32_t)i << 12);
            CP_ASYNC16(sb + SM_KV + off, kvsrc + off);
        }
        CP_COMMIT();
    }

    // ---- load Q tile (64 x 256): scale = (1/16)*log2(e) folded so P = ex2(S) ----
    {
        const float s = 0.0625f * 1.44269504f;
        const float4* gq = reinterpret_cast<const float4*>(q + ((size_t)(b * 1024 + q0)) * 256);
        #pragma unroll
        for (int i = 0; i < 16; i++) {
            int idx = tid + (i << 8);            // 4096 float4
            float4 v = gq[idx];
            int r = idx >> 6;
            uint32_t c2 = (uint32_t)(idx & 63) << 3;
            uint32_t ad = sb + SM_Q + (uint32_t)r * 512u + (c2 ^ ((uint32_t)(r & 7) << 4));
            STS64(ad, f2h2(v.x * s, v.y * s), f2h2(v.z * s, v.w * s));
        }
    }

    float oacc[64];                      // [mb*32 + dd*8 + tt*4 + i]
    #pragma unroll
    for (int i = 0; i < 64; i++) oacc[i] = 0.f;
    float rsum[4] = {0.f, 0.f, 0.f, 0.f};

    for (int t = 0; t < 8; t++) {
        CP_WAIT0();                      // this thread's tile-t chunks landed
        __syncthreads();                 // S1: all chunks visible; P free (PV(t-1) done)

        // ---- S = Qs . K^T  (m32 x n32, k256) ----
        float sacc[32];                  // [mb*16 + nb*8 + tt*4 + i]
        #pragma unroll
        for (int i = 0; i < 32; i++) sacc[i] = 0.f;
        #pragma unroll
        for (int kk = 0; kk < 16; kk++) {
            const uint32_t ka = (((uint32_t)kk << 5) | colselA) ^ swl;
            const uint32_t kb = (((uint32_t)kk << 5) | colselB) ^ swl;
            uint32_t a0, a1, a2, a3, a4, a5, a6, a7;
            LDSM_X4(a0, a1, a2, a3, aQ0 + ka);
            LDSM_X4(a4, a5, a6, a7, aQ1 + ka);
            #pragma unroll
            for (int nb = 0; nb < 2; nb++) {
                uint32_t b0, b1, b2, b3;
                LDSM_X4(b0, b1, b2, b3, (nb ? bK1 : bK0) + kb);
                MMA(&sacc[nb * 8 + 0],      a0, a1, a2, a3, b0, b1);
                MMA(&sacc[nb * 8 + 4],      a0, a1, a2, a3, b2, b3);
                MMA(&sacc[16 + nb * 8 + 0], a4, a5, a6, a7, b0, b1);
                MMA(&sacc[16 + nb * 8 + 4], a4, a5, a6, a7, b2, b3);
            }
        }

        // ---- P = ex2(S) -> smem; accumulate rowsums ----
        #pragma unroll
        for (int mb = 0; mb < 2; mb++) {
            const uint32_t base = pr0 + (uint32_t)(mb << 12);   // +16 rows
            #pragma unroll
            for (int j = 0; j < 4; j++) {                        // j = nb*2 + tt
                float* c = &sacc[mb * 16 + j * 4];
                float e0 = ex2(c[0]), e1 = ex2(c[1]);
                float e2 = ex2(c[2]), e3 = ex2(c[3]);
                rsum[mb * 2]     += e0 + e1;
                rsum[mb * 2 + 1] += e2 + e3;
                uint32_t col2 = ((uint32_t)(n0s + (j << 3) + (tig << 1)) << 1);
                STS32(base + (col2 ^ gx),         f2h2(e0, e1));
                STS32(base + 2048u + (col2 ^ gx), f2h2(e2, e3));
            }
        }
        __syncthreads();                 // S2: P fully exchanged

        // ---- O += P . V  (m32 x n64, k128) ----
        #pragma unroll
        for (int kk = 0; kk < 8; kk++) {
            const uint32_t ka = (((uint32_t)kk << 5) | colselA) ^ swl;
            uint32_t a0, a1, a2, a3, a4, a5, a6, a7;
            LDSM_X4(a0, a1, a2, a3, aP0 + ka);
            LDSM_X4(a4, a5, a6, a7, aP1 + ka);
            const uint32_t vrow = sb + SM_KV + (uint32_t)((kk << 4) + rV) * 512u;
            #pragma unroll
            for (int dd = 0; dd < 4; dd++) {
                uint32_t b0, b1, b2, b3;
                uint32_t va = vrow + ((((uint32_t)(d0q + (dd << 4)) << 1) | colselA) ^ swl);
                LDSM_X4_T(b0, b1, b2, b3, va);
                MMA(&oacc[dd * 8 + 0],      a0, a1, a2, a3, b0, b1);
                MMA(&oacc[dd * 8 + 4],      a0, a1, a2, a3, b2, b3);
                MMA(&oacc[32 + dd * 8 + 0], a4, a5, a6, a7, b0, b1);
                MMA(&oacc[32 + dd * 8 + 4], a4, a5, a6, a7, b2, b3);
            }
        }
        __syncthreads();                 // S3: PV(t) done -> KV buffer free

        // ---- issue cp.async for tile t+1 (wait at next S1; co-CTA covers) ----
        if (t < 7) {
            const unsigned char* src = kvsrc + ((uint32_t)(t + 1) << 16);
            const uint32_t off0 = (uint32_t)tid << 4;
            #pragma unroll
            for (int i = 0; i < 16; i++) {
                uint32_t off = off0 + ((uint32_t)i << 12);
                CP_ASYNC16(sb + SM_KV + off, src + off);
            }
            CP_COMMIT();
        }
    }

    // ---- rowsums (RS aliases P; final S3 guarantees P dead) ----
    #pragma unroll
    for (int i = 0; i < 4; i++) {
        rsum[i] += __shfl_xor_sync(0xffffffffu, rsum[i], 1);
        rsum[i] += __shfl_xor_sync(0xffffffffu, rsum[i], 2);
    }
    float* rs = reinterpret_cast<float*>(smem + SM_RS);   // [64][4]
    if (tig == 0) {
        rs[((m0 + g) << 2)      + (w & 3)] = rsum[0];
        rs[((m0 + 8 + g) << 2)  + (w & 3)] = rsum[1];
        rs[((m0 + 16 + g) << 2) + (w & 3)] = rsum[2];
        rs[((m0 + 24 + g) << 2) + (w & 3)] = rsum[3];
    }
    __syncthreads();

    // ---- normalize + store O ----
    #pragma unroll
    for (int mb = 0; mb < 2; mb++) {
        const int r0 = m0 + (mb << 4) + g;
        const float inv0 = 1.0f / (rs[(r0 << 2)] + rs[(r0 << 2) + 1] +
                                   rs[(r0 << 2) + 2] + rs[(r0 << 2) + 3]);
        const int r1 = r0 + 8;
        const float inv1 = 1.0f / (rs[(r1 << 2)] + rs[(r1 << 2) + 1] +
                                   rs[(r1 << 2) + 2] + rs[(r1 << 2) + 3]);
        float* o0 = out + ((size_t)(b * 1024 + q0 + r0)) * 256;
        float* o1 = o0 + 2048;           // +8 rows
        #pragma unroll
        for (int dd = 0; dd < 4; dd++) {
            #pragma unroll
            for (int tt = 0; tt < 2; tt++) {
                float* c = &oacc[mb * 32 + dd * 8 + tt * 4];
                int col = d0q + (dd << 4) + (tt << 3) + (tig << 1);
                float2 v0; v0.x = c[0] * inv0; v0.y = c[1] * inv0;
                float2 v1; v1.x = c[2] * inv1; v1.y = c[3] * inv1;
                *reinterpret_cast<float2*>(o0 + col) = v0;
                *reinterpret_cast<float2*>(o1 + col) = v1;
            }
        }
    }
}

extern "C" void kernel_launch(void* const* d_in, const int* in_sizes, int n_in,
                              void* d_out, int out_size) {
    const float* q  = (const float*)d_in[0];
    const float* kv = (const float*)d_in[1];
    float* out = (float*)d_out;
    cvt_kv_kernel<<<4096, 512>>>(kv);
    cudaFuncSetAttribute(attn_kernel, cudaFuncAttributeMaxDynamicSharedMemorySize, SMEM_BYTES);
    attn_kernel<<<1024, 256, SMEM_BYTES>>>(q, out);
}

// round 15
// speedup vs baseline: 1.8834x; 1.0035x over previous
#include <cuda_runtime.h>
#include <cuda_fp16.h>
#include <cstdint>
#include <cstddef>

// ---------------- global fp16 KV scratch (pre-converted, pre-swizzled) ----------------
// Layout: [b][t] tile images of 65536B, byte-identical to the smem KV buffer:
//   offset(r, k16) = r*512 + ((k16*16) ^ ((r&7)*16)),  r in [0,128), k16 in [0,32)
#define KV16_BYTES (64u * 8u * 65536u)   // 32 MB
__device__ __align__(16) unsigned char g_kv16[KV16_BYTES];

// ---------------- SMEM layout (bytes) ----------------
// Q  : [64 rows][256 d] fp16, row stride 512B, 16B-chunk XOR swizzle -> 32KB
// KV : single-buffered KV tile image -> 64KB (cp.async; strip-wise refill)
// P  : [64 rows][128 kv] fp16, row stride 256B -> 16KB
// RS : float[64][4] ALIASED over P (P dead after last PV)
#define SM_Q   0
#define SM_KV  32768
#define SM_P   98304
#define SM_RS  98304
#define SMEM_BYTES 114688

// ---------------- helpers ----------------
__device__ __forceinline__ uint32_t smem_u32(const void* p) {
    uint32_t a;
    asm("{ .reg .u64 t; cvta.to.shared.u64 t, %1; cvt.u32.u64 %0, t; }" : "=r"(a) : "l"(p));
    return a;
}
// pack two fp32 -> fp16x2, a in LOW half
__device__ __forceinline__ uint32_t f2h2(float a, float b) {
    uint32_t r;
    asm("cvt.rn.f16x2.f32 %0, %2, %1;" : "=r"(r) : "f"(a), "f"(b));
    return r;
}
__device__ __forceinline__ float ex2(float x) {
    float r;
    asm("ex2.approx.f32 %0, %1;" : "=f"(r) : "f"(x));
    return r;
}

#define STS32(addr, v) \
    asm volatile("st.shared.b32 [%0], %1;" :: "r"(addr), "r"(v) : "memory")
#define STS64(addr, v0, v1) \
    asm volatile("st.shared.v2.b32 [%0], {%1, %2};" :: "r"(addr), "r"(v0), "r"(v1) : "memory")

#define CP_ASYNC16(dst, src) \
    asm volatile("cp.async.cg.shared.global [%0], [%1], 16;" :: "r"(dst), "l"(src) : "memory")
#define CP_COMMIT()  asm volatile("cp.async.commit_group;" ::: "memory")
#define CP_WAIT0()   asm volatile("cp.async.wait_group 0;" ::: "memory")
#define NAMED_BAR(id, cnt) \
    asm volatile("bar.sync %0, %1;" :: "r"(id), "r"(cnt) : "memory")

#define LDSM_X4(r0, r1, r2, r3, addr)                                          \
    asm volatile("ldmatrix.sync.aligned.m8n8.x4.shared.b16 {%0,%1,%2,%3}, [%4];" \
        : "=r"(r0), "=r"(r1), "=r"(r2), "=r"(r3) : "r"(addr))
#define LDSM_X4_T(r0, r1, r2, r3, addr)                                        \
    asm volatile("ldmatrix.sync.aligned.m8n8.x4.trans.shared.b16 {%0,%1,%2,%3}, [%4];" \
        : "=r"(r0), "=r"(r1), "=r"(r2), "=r"(r3) : "r"(addr))

// D(f32x4) += A(f16, m16k16) * B(f16, k16n8)
#define MMA(c, a0, a1, a2, a3, b0, b1)                                         \
    asm volatile("mma.sync.aligned.m16n8k16.row.col.f32.f16.f16.f32 "          \
        "{%0,%1,%2,%3},{%4,%5,%6,%7},{%8,%9},{%0,%1,%2,%3};"                   \
        : "+f"((c)[0]), "+f"((c)[1]), "+f"((c)[2]), "+f"((c)[3])               \
        : "r"(a0), "r"(a1), "r"(a2), "r"(a3), "r"(b0), "r"(b1))

// ---------------- pre-pass: fp32 KV -> fp16 swizzled tile images ----------------
__global__ void __launch_bounds__(512, 4)
cvt_kv_kernel(const float* __restrict__ kv)
{
    uint32_t cid = blockIdx.x * 512u + threadIdx.x;
    uint32_t j  = cid & 4095u;           // chunk within tile
    uint32_t bt = cid >> 12;             // b*8 + t
    uint32_t r = j >> 5, k = j & 31u;
    uint32_t b = bt >> 3, t = bt & 7u;
    size_t fbase = (size_t)b * 262144 + (size_t)(t * 128u + r) * 256 + (size_t)(k * 8u);
    float4 v0 = *reinterpret_cast<const float4*>(kv + fbase);
    float4 v1 = *reinterpret_cast<const float4*>(kv + fbase + 4);
    uint4 o;
    o.x = f2h2(v0.x, v0.y); o.y = f2h2(v0.z, v0.w);
    o.z = f2h2(v1.x, v1.y); o.w = f2h2(v1.z, v1.w);
    uint32_t doff = (bt << 16) + r * 512u + ((k << 4) ^ ((r & 7u) << 4));
    *reinterpret_cast<uint4*>(g_kv16 + doff) = o;
}

// ---------------- main kernel ----------------
// grid 1024 = 64 batches x 16 q-tiles of 64 rows; block 256 = 8 warps; 2 CTAs/SM.
// S  phase: warp w -> rows [32*(w>>2), +32), kv cols [32*(w&3), +32)   (m32 x n32)
// PV phase: warp w -> rows [32*(w>>2), +32), d  cols [64*(w&3), +64)   (m32 x n64)
// Barriers: S1 = block (KV visible / P reusable). P exchange = named bar per
// m-group (128 thr). KV strip refill: after own PV, sync only with the dq
// partner warp (named bar, 64 thr), then cp.async own strip of tile t+1.
__global__ void __launch_bounds__(256, 2)
attn_kernel(const float* __restrict__ q, float* __restrict__ out)
{
    extern __shared__ __align__(16) char smem[];
    const uint32_t sb = smem_u32(smem);
    const int tid  = threadIdx.x;
    const int lane = tid & 31, w = tid >> 5;
    const int b  = blockIdx.x >> 4;
    const int q0 = (blockIdx.x & 15) << 6;
    const int g = lane >> 2, tig = lane & 3;
    const int lj = lane & 7, sel = lane >> 3;
    const uint32_t swl = (uint32_t)lj << 4;
    const uint32_t gx  = (uint32_t)g << 4;

    const int mg  = w >> 2;             // m-group (rows 32*mg..+32)
    const int dq  = w & 3;              // kv-quarter (S) / d-quarter (PV)
    const int m0  = mg << 5;
    const int n0s = dq << 5;
    const int d0q = dq << 6;

    // fragment lane geometry (validated R8-R14)
    const uint32_t colselA = (uint32_t)(sel >> 1) << 4;  // A-type and V-trans
    const uint32_t colselB = (uint32_t)(sel & 1) << 4;   // B-type non-trans
    const int rA = lj + ((sel & 1) << 3);
    const int rB = lj + ((sel >> 1) << 3);
    const int rV = lj + ((sel & 1) << 3);

    const uint32_t aQ0 = sb + SM_Q + (uint32_t)(m0 + rA) * 512u;
    const uint32_t aQ1 = aQ0 + 16u * 512u;
    const uint32_t aP0 = sb + SM_P + (uint32_t)(m0 + rA) * 256u;
    const uint32_t aP1 = aP0 + 16u * 256u;
    const uint32_t bK0 = sb + SM_KV + (uint32_t)(n0s + rB) * 512u;
    const uint32_t bK1 = bK0 + 16u * 512u;
    const uint32_t pr0 = sb + SM_P + (uint32_t)(m0 + g) * 256u;

    const unsigned char* kvsrc = g_kv16 + ((size_t)(b << 3) << 16);

    // per-warp KV refill strip: rows [64*mg, +64) x chunk-slots [8*dq, +8)
    // (slot set is closed under the XOR swizzle since lj < 8)
    const uint32_t coff = (uint32_t)((mg * 64 + (lane >> 3)) * 512
                                   + (dq * 8 + (lane & 7)) * 16);

    // ---- prologue: issue cp.async for KV tile 0 (64KB over 256 threads) ----
    {
        const uint32_t off0 = (uint32_t)tid << 4;
        #pragma unroll
        for (int i = 0; i < 16; i++) {
            uint32_t off = off0 + ((uint32_t)i << 12);
            CP_ASYNC16(sb + SM_KV + off, kvsrc + off);
        }
        CP_COMMIT();
    }

    // ---- load Q tile (64 x 256): scale = (1/16)*log2(e) folded so P = ex2(S) ----
    {
        const float s = 0.0625f * 1.44269504f;
        const float4* gq = reinterpret_cast<const float4*>(q + ((size_t)(b * 1024 + q0)) * 256);
        #pragma unroll
        for (int i = 0; i < 16; i++) {
            int idx = tid + (i << 8);            // 4096 float4
            float4 v = gq[idx];
            int r = idx >> 6;
            uint32_t c2 = (uint32_t)(idx & 63) << 3;
            uint32_t ad = sb + SM_Q + (uint32_t)r * 512u + (c2 ^ ((uint32_t)(r & 7) << 4));
            STS64(ad, f2h2(v.x * s, v.y * s), f2h2(v.z * s, v.w * s));
        }
    }

    float oacc[64];                      // [mb*32 + dd*8 + tt*4 + i]
    #pragma unroll
    for (int i = 0; i < 64; i++) oacc[i] = 0.f;
    float rsum[4] = {0.f, 0.f, 0.f, 0.f};

    for (int t = 0; t < 8; t++) {
        CP_WAIT0();                      // own cp.async groups landed
        __syncthreads();                 // S1: all strips visible; P free; Q ready

        // ---- S = Qs . K^T  (m32 x n32, k256) ----
        float sacc[32];                  // [mb*16 + nb*8 + tt*4 + i]
        #pragma unroll
        for (int i = 0; i < 32; i++) sacc[i] = 0.f;
        #pragma unroll
        for (int kk = 0; kk < 16; kk++) {
            const uint32_t ka = (((uint32_t)kk << 5) | colselA) ^ swl;
            const uint32_t kb = (((uint32_t)kk << 5) | colselB) ^ swl;
            uint32_t a0, a1, a2, a3, a4, a5, a6, a7;
            LDSM_X4(a0, a1, a2, a3, aQ0 + ka);
            LDSM_X4(a4, a5, a6, a7, aQ1 + ka);
            #pragma unroll
            for (int nb = 0; nb < 2; nb++) {
                uint32_t b0, b1, b2, b3;
                LDSM_X4(b0, b1, b2, b3, (nb ? bK1 : bK0) + kb);
                MMA(&sacc[nb * 8 + 0],      a0, a1, a2, a3, b0, b1);
                MMA(&sacc[nb * 8 + 4],      a0, a1, a2, a3, b2, b3);
                MMA(&sacc[16 + nb * 8 + 0], a4, a5, a6, a7, b0, b1);
                MMA(&sacc[16 + nb * 8 + 4], a4, a5, a6, a7, b2, b3);
            }
        }

        // ---- P = ex2(S) -> smem; accumulate rowsums ----
        #pragma unroll
        for (int mb = 0; mb < 2; mb++) {
            const uint32_t base = pr0 + (uint32_t)(mb << 12);   // +16 rows
            #pragma unroll
            for (int j = 0; j < 4; j++) {                        // j = nb*2 + tt
                float* c = &sacc[mb * 16 + j * 4];
                float e0 = ex2(c[0]), e1 = ex2(c[1]);
                float e2 = ex2(c[2]), e3 = ex2(c[3]);
                rsum[mb * 2]     += e0 + e1;
                rsum[mb * 2 + 1] += e2 + e3;
                uint32_t col2 = ((uint32_t)(n0s + (j << 3) + (tig << 1)) << 1);
                STS32(base + (col2 ^ gx),         f2h2(e0, e1));
                STS32(base + 2048u + (col2 ^ gx), f2h2(e2, e3));
            }
        }
        NAMED_BAR(1 + mg, 128);          // P[mg] exchanged among its 4 warps

        // ---- O += P . V  (m32 x n64, k128) ----
        #pragma unroll
        for (int kk = 0; kk < 8; kk++) {
            const uint32_t ka = (((uint32_t)kk << 5) | colselA) ^ swl;
            uint32_t a0, a1, a2, a3, a4, a5, a6, a7;
            LDSM_X4(a0, a1, a2, a3, aP0 + ka);
            LDSM_X4(a4, a5, a6, a7, aP1 + ka);
            const uint32_t vrow = sb + SM_KV + (uint32_t)((kk << 4) + rV) * 512u;
            #pragma unroll
            for (int dd = 0; dd < 4; dd++) {
                uint32_t b0, b1, b2, b3;
                uint32_t va = vrow + ((((uint32_t)(d0q + (dd << 4)) << 1) | colselA) ^ swl);
                LDSM_X4_T(b0, b1, b2, b3, va);
                MMA(&oacc[dd * 8 + 0],      a0, a1, a2, a3, b0, b1);
                MMA(&oacc[dd * 8 + 4],      a0, a1, a2, a3, b2, b3);
                MMA(&oacc[32 + dd * 8 + 0], a4, a5, a6, a7, b0, b1);
                MMA(&oacc[32 + dd * 8 + 4], a4, a5, a6, a7, b2, b3);
            }
        }

        // ---- strip refill: only the dq-partner reads this V strip ----
        NAMED_BAR(3 + dq, 64);           // both mg warps of this dq done with strip
        if (t < 7) {
            const unsigned char* src = kvsrc + ((uint32_t)(t + 1) << 16) + coff;
            const uint32_t dst = sb + SM_KV + coff;
            #pragma unroll
            for (int i = 0; i < 16; i++) {
                CP_ASYNC16(dst + ((uint32_t)i << 11), src + ((uint32_t)i << 11));
            }
            CP_COMMIT();
        }
    }

    __syncthreads();                     // all PV done -> P region reusable as RS

    // ---- rowsums: quad-reduce, combine 4 kv-quarters via smem ----
    #pragma unroll
    for (int i = 0; i < 4; i++) {
        rsum[i] += __shfl_xor_sync(0xffffffffu, rsum[i], 1);
        rsum[i] += __shfl_xor_sync(0xffffffffu, rsum[i], 2);
    }
    float* rs = reinterpret_cast<float*>(smem + SM_RS);   // [64][4]
    if (tig == 0) {
        rs[((m0 + g) << 2)      + dq] = rsum[0];
        rs[((m0 + 8 + g) << 2)  + dq] = rsum[1];
        rs[((m0 + 16 + g) << 2) + dq] = rsum[2];
        rs[((m0 + 24 + g) << 2) + dq] = rsum[3];
    }
    __syncthreads();

    // ---- normalize + store O ----
    #pragma unroll
    for (int mb = 0; mb < 2; mb++) {
        const int r0 = m0 + (mb << 4) + g;
        const float inv0 = 1.0f / (rs[(r0 << 2)] + rs[(r0 << 2) + 1] +
                                   rs[(r0 << 2) + 2] + rs[(r0 << 2) + 3]);
        const int r1 = r0 + 8;
        const float inv1 = 1.0f / (rs[(r1 << 2)] + rs[(r1 << 2) + 1] +
                                   rs[(r1 << 2) + 2] + rs[(r1 << 2) + 3]);
        float* o0 = out + ((size_t)(b * 1024 + q0 + r0)) * 256;
        float* o1 = o0 + 2048;           // +8 rows
        #pragma unroll
        for (int dd = 0; dd < 4; dd++) {
            #pragma unroll
            for (int tt = 0; tt < 2; tt++) {
                float* c = &oacc[mb * 32 + dd * 8 + tt * 4];
                int col = d0q + (dd << 4) + (tt << 3) + (tig << 1);
                float2 v0; v0.x = c[0] * inv0; v0.y = c[1] * inv0;
                float2 v1; v1.x = c[2] * inv1; v1.y = c[3] * inv1;
                *reinterpret_cast<float2*>(o0 + col) = v0;
                *reinterpret_cast<float2*>(o1 + col) = v1;
            }
        }
    }
}

extern "C" void kernel_launch(void* const* d_in, const int* in_sizes, int n_in,
                              void* d_out, int out_size) {
    const float* q  = (const float*)d_in[0];
    const float* kv = (const float*)d_in[1];
    float* out = (float*)d_out;
    cvt_kv_kernel<<<4096, 512>>>(kv);
    cudaFuncSetAttribute(attn_kernel, cudaFuncAttributeMaxDynamicSharedMemorySize, SMEM_BYTES);
    attn_kernel<<<1024, 256, SMEM_BYTES>>>(q, out);
}